// round 3
// baseline (speedup 1.0000x reference)
#include <cuda_runtime.h>
#include <math.h>

#define BB 2
#define SS 1024
#define EE 512
#define HH 64
#define DKK 8
#define FF 2048
#define ROWS (BB*SS)   // 2048

// ---------------- scratch (static device globals; no allocation) ----------------
__device__ float g_q[BB*HH*SS*DKK];     // [B,H,S,8]   4 MB
__device__ float g_attnv[ROWS*EE];      // attention out, [B*S, E]
__device__ float g_comb[ROWS*EE];       // combine GEMM out
__device__ float g_x1[ROWS*EE];
__device__ float g_qf[ROWS*EE];
__device__ float g_hdn[ROWS*FF];        // 16 MB
__device__ float g_ffn[ROWS*EE];

// ---------------- kernel 1: quantum ring expvals (q=k=v) ----------------
__global__ void qkv_kernel(const float* __restrict__ x, const float* __restrict__ theta,
                           float* __restrict__ q) {
    int idx = blockIdx.x * blockDim.x + threadIdx.x;   // over B*S*H
    if (idx >= BB * SS * HH) return;
    int h  = idx & (HH - 1);
    int bs = idx >> 6;                                  // b*S + s
    const float* xp = x + (size_t)bs * EE + h * DKK;

    float c[8];
#pragma unroll
    for (int d = 0; d < 8; d++) c[d] = cosf(xp[d] + theta[d]);

    float out[8];
    float run = c[0];
#pragma unroll
    for (int i = 1; i < 8; i++) { run *= c[i]; out[i] = run; }
    float p = c[1];
#pragma unroll
    for (int i = 2; i < 8; i++) p *= c[i];
    out[0] = p;

    int b = bs >> 10;          // / SS
    int s = bs & (SS - 1);
    float* qp = q + ((size_t)(b * HH + h) * SS + s) * 8;
    *(float4*)qp       = make_float4(out[0], out[1], out[2], out[3]);
    *(float4*)(qp + 4) = make_float4(out[4], out[5], out[6], out[7]);
}

// ---------------- kernel 2: attention per (b,h); whole head in SMEM ----------------
// Scores bounded by |8/sqrt(8)| = 2.83 -> softmax without max subtraction is safe.
__global__ void __launch_bounds__(1024, 1)
attn_kernel(const float* __restrict__ q, float* __restrict__ attnv) {
    __shared__ float4 ksh[SS * 2];     // 1024 rows x 8 floats = 32 KB
    int bh = blockIdx.x;               // 0..127
    int b = bh >> 6, h = bh & 63;
    int tid = threadIdx.x;             // query row

    const float4* qp = (const float4*)(q + (size_t)bh * SS * 8);
    ksh[tid * 2]     = qp[tid * 2];
    ksh[tid * 2 + 1] = qp[tid * 2 + 1];
    __syncthreads();

    float4 qa = ksh[tid * 2];
    float4 qb = ksh[tid * 2 + 1];
    const float scale = 0.35355339059327373f;   // 1/sqrt(8)

    float sum = 0.f;
    float a0=0,a1=0,a2=0,a3=0,a4=0,a5=0,a6=0,a7=0;

#pragma unroll 4
    for (int t = 0; t < SS; t++) {
        float4 ka = ksh[2 * t];       // broadcast: all lanes same address
        float4 kb = ksh[2 * t + 1];
        float s = qa.x*ka.x + qa.y*ka.y + qa.z*ka.z + qa.w*ka.w
                + qb.x*kb.x + qb.y*kb.y + qb.z*kb.z + qb.w*kb.w;
        float e = __expf(s * scale);
        sum += e;
        a0 += e * ka.x; a1 += e * ka.y; a2 += e * ka.z; a3 += e * ka.w;
        a4 += e * kb.x; a5 += e * kb.y; a6 += e * kb.z; a7 += e * kb.w;
    }
    float inv = 1.f / sum;
    float* op = attnv + (size_t)(b * SS + tid) * EE + h * 8;
    *(float4*)op       = make_float4(a0*inv, a1*inv, a2*inv, a3*inv);
    *(float4*)(op + 4) = make_float4(a4*inv, a5*inv, a6*inv, a7*inv);
}

// ---------------- kernel 3: double-buffered register-tiled SGEMM ----------------
// C = op(A@B + bias). BM=128, BN=64, BK=16, 256 threads, 8x4 micro-tile.
// Row-major A[M,K], B[K,N]. M,N,K multiples of tile sizes (asserted by launch).
template<int RELU>
__global__ void __launch_bounds__(256)
sgemm_kernel(const float* __restrict__ A, const float* __restrict__ B,
             const float* __restrict__ bias, float* __restrict__ C,
             int M, int N, int K) {
    const int BM = 128, BN = 64, BK = 16;
    __shared__ float As[2][BK][BM];
    __shared__ float Bs[2][BK][BN];

    int tid = threadIdx.x;
    int tx = tid & 15;       // N dir: 16 * 4 = 64
    int ty = tid >> 4;       // M dir: 16 * 8 = 128
    int rowBase = blockIdx.y * BM;
    int colBase = blockIdx.x * BN;

    float acc[8][4];
#pragma unroll
    for (int i = 0; i < 8; i++)
#pragma unroll
        for (int j = 0; j < 4; j++) acc[i][j] = 0.f;

    int ar = tid >> 1;             // A row within tile (0..127)
    int ac = (tid & 1) << 3;       // A col offset (0 or 8)
    int br = tid >> 4;             // B row within k-tile (0..15)
    int bc = (tid & 15) << 2;      // B col offset

    const float* Aptr = A + (size_t)(rowBase + ar) * K + ac;
    const float* Bptr = B + (size_t)br * N + colBase + bc;

    // ---- preload k-tile 0 into buffer 0 ----
    float4 va0 = *(const float4*)(Aptr);
    float4 va1 = *(const float4*)(Aptr + 4);
    float4 vb  = *(const float4*)(Bptr);
    As[0][ac + 0][ar] = va0.x; As[0][ac + 1][ar] = va0.y;
    As[0][ac + 2][ar] = va0.z; As[0][ac + 3][ar] = va0.w;
    As[0][ac + 4][ar] = va1.x; As[0][ac + 5][ar] = va1.y;
    As[0][ac + 6][ar] = va1.z; As[0][ac + 7][ar] = va1.w;
    *(float4*)&Bs[0][br][bc] = vb;
    __syncthreads();

    int buf = 0;
    for (int k0 = 0; k0 < K; k0 += BK) {
        // prefetch next k-tile into registers (overlaps with compute below)
        bool more = (k0 + BK) < K;
        if (more) {
            va0 = *(const float4*)(Aptr + k0 + BK);
            va1 = *(const float4*)(Aptr + k0 + BK + 4);
            vb  = *(const float4*)(Bptr + (size_t)(k0 + BK) * N);
        }

#pragma unroll
        for (int kk = 0; kk < BK; kk++) {
            float a[8], bv[4];
            *(float4*)(a)     = *(const float4*)&As[buf][kk][ty * 8];
            *(float4*)(a + 4) = *(const float4*)&As[buf][kk][ty * 8 + 4];
            *(float4*)(bv)    = *(const float4*)&Bs[buf][kk][tx * 4];
#pragma unroll
            for (int i = 0; i < 8; i++)
#pragma unroll
                for (int j = 0; j < 4; j++)
                    acc[i][j] += a[i] * bv[j];
        }

        if (more) {
            int nb = buf ^ 1;
            As[nb][ac + 0][ar] = va0.x; As[nb][ac + 1][ar] = va0.y;
            As[nb][ac + 2][ar] = va0.z; As[nb][ac + 3][ar] = va0.w;
            As[nb][ac + 4][ar] = va1.x; As[nb][ac + 5][ar] = va1.y;
            As[nb][ac + 6][ar] = va1.z; As[nb][ac + 7][ar] = va1.w;
            *(float4*)&Bs[nb][br][bc] = vb;
            __syncthreads();
            buf = nb;
        }
    }

    float4 bsv = *(const float4*)&bias[colBase + tx * 4];
#pragma unroll
    for (int i = 0; i < 8; i++) {
        int r = rowBase + ty * 8 + i;
        float4 v = make_float4(acc[i][0] + bsv.x, acc[i][1] + bsv.y,
                               acc[i][2] + bsv.z, acc[i][3] + bsv.w);
        if (RELU) {
            v.x = fmaxf(v.x, 0.f); v.y = fmaxf(v.y, 0.f);
            v.z = fmaxf(v.z, 0.f); v.w = fmaxf(v.w, 0.f);
        }
        *(float4*)(C + (size_t)r * N + colBase + tx * 4) = v;
    }
}

// ---------------- kernel 4: layernorm (+ optional fused quantum-FFN input) ----------------
__device__ __forceinline__ float block_reduce_256(float v, float* red) {
    int tid = threadIdx.x;
#pragma unroll
    for (int o = 16; o; o >>= 1) v += __shfl_xor_sync(0xffffffffu, v, o);
    if ((tid & 31) == 0) red[tid >> 5] = v;
    __syncthreads();
    float t = red[0] + red[1] + red[2] + red[3] + red[4] + red[5] + red[6] + red[7];
    __syncthreads();
    return t;
}

__global__ void __launch_bounds__(256)
ln_kernel(const float* __restrict__ xa, const float* __restrict__ xb,
          const float* __restrict__ w, const float* __restrict__ bias,
          float* __restrict__ out,
          const float* __restrict__ theta, float* __restrict__ qf) {
    __shared__ float red[8];
    int row = blockIdx.x;
    int tid = threadIdx.x;   // 256 threads, 2 elems each (E=512)
    const float* pa = xa + (size_t)row * EE;
    const float* pb = xb + (size_t)row * EE;

    float v0 = pa[tid]       + pb[tid];
    float v1 = pa[tid + 256] + pb[tid + 256];

    float total = block_reduce_256(v0 + v1, red);
    float mu = total * (1.f / EE);
    float d0 = v0 - mu, d1 = v1 - mu;
    float sq = block_reduce_256(d0 * d0 + d1 * d1, red);
    float r = rsqrtf(sq * (1.f / EE) + 1e-5f);

    float o0 = d0 * r * w[tid]       + bias[tid];
    float o1 = d1 * r * w[tid + 256] + bias[tid + 256];
    out[(size_t)row * EE + tid]       = o0;
    out[(size_t)row * EE + tid + 256] = o1;
    if (qf) {
        qf[(size_t)row * EE + tid]       = cosf(o0) * cosf(theta[tid]);
        qf[(size_t)row * EE + tid + 256] = cosf(o1) * cosf(theta[tid + 256]);
    }
}

// ---------------- launch ----------------
extern "C" void kernel_launch(void* const* d_in, const int* in_sizes, int n_in,
                              void* d_out, int out_size) {
    const float* x          = (const float*)d_in[0];
    const float* theta_attn = (const float*)d_in[1];
    const float* w_combine  = (const float*)d_in[2];
    const float* b_combine  = (const float*)d_in[3];
    const float* theta_ffn  = (const float*)d_in[4];
    const float* w1         = (const float*)d_in[5];
    const float* b1         = (const float*)d_in[6];
    const float* w2         = (const float*)d_in[7];
    const float* b2         = (const float*)d_in[8];
    const float* ln1_w      = (const float*)d_in[9];
    const float* ln1_b      = (const float*)d_in[10];
    const float* ln2_w      = (const float*)d_in[11];
    const float* ln2_b      = (const float*)d_in[12];
    float* out = (float*)d_out;

    float *q, *attnv, *comb, *x1, *qf, *hdn, *ffn;
    cudaGetSymbolAddress((void**)&q,     g_q);
    cudaGetSymbolAddress((void**)&attnv, g_attnv);
    cudaGetSymbolAddress((void**)&comb,  g_comb);
    cudaGetSymbolAddress((void**)&x1,    g_x1);
    cudaGetSymbolAddress((void**)&qf,    g_qf);
    cudaGetSymbolAddress((void**)&hdn,   g_hdn);
    cudaGetSymbolAddress((void**)&ffn,   g_ffn);

    // 1) quantum circuit -> q  [B,H,S,8]
    qkv_kernel<<<(BB * SS * HH + 255) / 256, 256>>>(x, theta_attn, q);

    // 2) attention per head -> attnv [B*S, E]
    attn_kernel<<<BB * HH, 1024>>>(q, attnv);

    // 3) combine GEMM: [2048,512] @ [512,512] + b
    {
        dim3 grid(EE / 64, ROWS / 128);
        sgemm_kernel<0><<<grid, 256>>>(attnv, w_combine, b_combine, comb, ROWS, EE, EE);
    }

    // 4) LN1 + fused qf = cos(x1)*cos(theta_ffn)
    ln_kernel<<<ROWS, 256>>>(x, comb, ln1_w, ln1_b, x1, theta_ffn, qf);

    // 5) FFN GEMM1 + relu: [2048,512] @ [512,2048]
    {
        dim3 grid(FF / 64, ROWS / 128);
        sgemm_kernel<1><<<grid, 256>>>(qf, w1, b1, hdn, ROWS, FF, EE);
    }

    // 6) FFN GEMM2: [2048,2048] @ [2048,512]
    {
        dim3 grid(EE / 64, ROWS / 128);
        sgemm_kernel<0><<<grid, 256>>>(hdn, w2, b2, ffn, ROWS, EE, FF);
    }

    // 7) LN2 -> output
    ln_kernel<<<ROWS, 256>>>(x1, ffn, ln2_w, ln2_b, out, nullptr, nullptr);
}